// round 4
// baseline (speedup 1.0000x reference)
#include <cuda_runtime.h>
#include <math.h>
#include <stdint.h>

#define NN 1024
#define DD 64
#define TI 4
#define TROWS 64          // j-tile rows
#define NTILES (NN / TROWS)
#define NBUF 4            // smem stage buffers (3 in flight)
#define TILE_BYTES (TROWS * DD * 4)   // 16384

// Scratch (device globals — no allocation allowed in kernel_launch).
__device__ float g_s1[NN];          // x @ w1   (softmax logits per source node j)
__device__ float g_ssrc[NN * DD];   // x @ F1^T (per source node j)
__device__ float g_t[NN * DD];      // x @ F2^T + f_b (per target node i)

// ---- packed fp32x2 helpers (sm_100a: ADD2 / FFMA2) -------------------------
__device__ __forceinline__ float2 f2_add(float2 a, float2 b) {
    float2 c;
    asm("add.rn.f32x2 %0, %1, %2;"
        : "=l"(*reinterpret_cast<unsigned long long*>(&c))
        : "l"(*reinterpret_cast<const unsigned long long*>(&a)),
          "l"(*reinterpret_cast<const unsigned long long*>(&b)));
    return c;
}
__device__ __forceinline__ float2 f2_fma(float2 a, float2 b, float2 c) {
    float2 d;
    asm("fma.rn.f32x2 %0, %1, %2, %3;"
        : "=l"(*reinterpret_cast<unsigned long long*>(&d))
        : "l"(*reinterpret_cast<const unsigned long long*>(&a)),
          "l"(*reinterpret_cast<const unsigned long long*>(&b)),
          "l"(*reinterpret_cast<const unsigned long long*>(&c)));
    return d;
}

__device__ __forceinline__ void cp16(uint32_t saddr, const void* g) {
    asm volatile("cp.async.cg.shared.global [%0], [%1], 16;"
                 :: "r"(saddr), "l"(g) : "memory");
}

// ---------------------------------------------------------------------------
// Kernel A: per-node projections. 128 blocks x 512 threads, 8 nodes/block.
// ---------------------------------------------------------------------------
__global__ __launch_bounds__(512, 1) void gat_pre_kernel(
    const float* __restrict__ x,
    const float* __restrict__ f_w,   // [DD][2*DD] row-major
    const float* __restrict__ f_b,   // [DD]
    const float* __restrict__ w_w)   // [1][2*DD]
{
    __shared__ float fw_sh[128][65]; // fw_sh[k][d] = f_w[d*128 + k]
    __shared__ float xs[8][DD];
    __shared__ float w1_sh[DD];
    __shared__ float sred[8][2];

    const int tid   = threadIdx.x;
    const int node0 = blockIdx.x * 8;

    for (int i = tid; i < DD * 128; i += 512)
        fw_sh[i & 127][i >> 7] = f_w[i];          // stride-65 rows: no conflicts
    if (tid < DD) w1_sh[tid] = w_w[tid];
    xs[tid >> 6][tid & 63] = x[node0 * DD + tid];
    __syncthreads();

    const int ln   = tid >> 6;
    const int d    = tid & 63;
    const int node = node0 + ln;

    float a1 = 0.f, a2 = 0.f;
#pragma unroll
    for (int k = 0; k < DD; ++k) {
        float xa = xs[ln][k];
        a1 = fmaf(xa, fw_sh[k][d], a1);
        a2 = fmaf(xa, fw_sh[DD + k][d], a2);
    }
    g_ssrc[node * DD + d] = a1;
    g_t[node * DD + d]    = a2 + f_b[d];

    float p = xs[ln][d] * w1_sh[d];
#pragma unroll
    for (int off = 16; off > 0; off >>= 1)
        p += __shfl_down_sync(0xffffffffu, p, off);
    if ((tid & 31) == 0) sred[ln][(tid >> 5) & 1] = p;
    __syncthreads();
    if (d == 0) g_s1[node] = sred[ln][0] + sred[ln][1];
}

// ---------------------------------------------------------------------------
// Kernel B: masked softmax + weighted-relu contraction, cp.async pipelined.
// 256 blocks (TI=4 rows) x 512 threads, 2 CTAs/SM, ~101 KB dynamic smem.
//   - 3 s_src tiles prefetched via LDGSTS at kernel entry (overlap softmax)
//   - per tile: warp w handles its 4 j rows from smem (LDS only, no LDG)
// ---------------------------------------------------------------------------
#define SMEM_ATT   0
#define SMEM_STAGE 32768
#define SMEM_S1    (32768 + NBUF * TILE_BYTES)          // 98304
#define SMEM_T     (SMEM_S1 + NN * 4)                   // 102400
#define SMEM_WSUM  (SMEM_T + TI * DD * 4)               // 103424
#define SMEM_RINV  (SMEM_WSUM + 16 * TI * 4)            // 103680
#define SMEM_TOTAL (SMEM_RINV + 64)                     // 103744

__global__ __launch_bounds__(512, 2) void gat_main_kernel(
    const int* __restrict__ adj,
    float* __restrict__ out)
{
    extern __shared__ char dsm[];
    float2* att2   = reinterpret_cast<float2*>(dsm + SMEM_ATT);   // [NN*TI]
    float*  stage  = reinterpret_cast<float*>(dsm + SMEM_STAGE);  // [NBUF][64*64]
    float*  s1_sh  = reinterpret_cast<float*>(dsm + SMEM_S1);
    float*  t_sh   = reinterpret_cast<float*>(dsm + SMEM_T);
    float*  wsum   = reinterpret_cast<float*>(dsm + SMEM_WSUM);   // [16][TI]
    float*  rowinv = reinterpret_cast<float*>(dsm + SMEM_RINV);

    const int tid  = threadIdx.x;
    const int row0 = blockIdx.x * TI;
    const int wid  = tid >> 5;
    const int lane = tid & 31;

    // --- kick off async prefetch of the first 3 s_src tiles -----------------
    const uint32_t stage_s =
        (uint32_t)__cvta_generic_to_shared(stage) + (uint32_t)tid * 16u;
    const char* gsrc = reinterpret_cast<const char*>(g_ssrc) + tid * 16;
#pragma unroll
    for (int t = 0; t < 3; ++t) {
        uint32_t dst = stage_s + (t & (NBUF - 1)) * TILE_BYTES;
        const char* src = gsrc + t * TILE_BYTES;
        cp16(dst, src);
        cp16(dst + 8192, src + 8192);
        asm volatile("cp.async.commit_group;" ::: "memory");
    }

    for (int i = tid; i < NN; i += 512) s1_sh[i] = g_s1[i];
    if (tid < TI * DD) t_sh[tid] = g_t[row0 * DD + tid];
    __syncthreads();

    // --- softmax numerators: e[j][r] = adj[r][j]>0 ? exp(s1[j]) : 0 ---------
    {
        float ls[TI] = {0.f, 0.f, 0.f, 0.f};
#pragma unroll
        for (int k = 0; k < 2; ++k) {
            int j = wid * 64 + k * 32 + lane;
            float ev = __expf(s1_sh[j]);
#pragma unroll
            for (int rr = 0; rr < TI; ++rr) {
                int a = adj[(row0 + rr) * NN + j];          // coalesced
                float e = (a > 0) ? ev : 0.f;
                att2[j * TI + rr] = make_float2(e, e);
                ls[rr] += e;
            }
        }
#pragma unroll
        for (int rr = 0; rr < TI; ++rr) {
            float v = ls[rr];
#pragma unroll
            for (int off = 16; off > 0; off >>= 1)
                v += __shfl_xor_sync(0xffffffffu, v, off);
            if (lane == 0) wsum[wid * TI + rr] = v;
        }
    }
    __syncthreads();
    if (tid < TI) {
        float s = 0.f;
#pragma unroll
        for (int g = 0; g < 16; ++g) s += wsum[g * TI + tid];
        rowinv[tid] = 1.f / s;
    }

    // --- pipelined contraction ----------------------------------------------
    const int h = lane >> 4;         // 0: rows {0,1}, 1: rows {2,3}
    const int q = lane & 15;         // d quad: d = 4q..4q+3

    float2 t2[2][2];
#pragma unroll
    for (int rr = 0; rr < 2; ++rr)
#pragma unroll
        for (int p = 0; p < 2; ++p)
            t2[rr][p] = *reinterpret_cast<const float2*>(
                &t_sh[(2 * h + rr) * DD + 4 * q + 2 * p]);

    float2 acc[2][2];
    acc[0][0] = acc[0][1] = acc[1][0] = acc[1][1] = make_float2(0.f, 0.f);

    for (int t = 0; t < NTILES; ++t) {
        asm volatile("cp.async.wait_group 2;" ::: "memory");
        __syncthreads();   // tile t visible to all; compute(t-1) done by all

        if (t + 3 < NTILES) {   // issue into buf (t+3)&3  (!= current buf t&3)
            uint32_t dst = stage_s + ((t + 3) & (NBUF - 1)) * TILE_BYTES;
            const char* src = gsrc + (t + 3) * TILE_BYTES;
            cp16(dst, src);
            cp16(dst + 8192, src + 8192);
            asm volatile("cp.async.commit_group;" ::: "memory");
        }

        const float* sbuf = stage + (t & (NBUF - 1)) * (TROWS * DD);
        const float4* ap4 = reinterpret_cast<const float4*>(
            att2 + (t * TROWS) * TI) + h;

#pragma unroll
        for (int i = 0; i < 4; ++i) {
            int jj = (wid << 2) + i;                 // tile-local j row
            float4 s4 = *reinterpret_cast<const float4*>(sbuf + jj * DD + 4 * q);
            float4 e4 = ap4[jj * 2];                 // {e2h,e2h,e2h+1,e2h+1}
            float2 sa = make_float2(s4.x, s4.y);
            float2 sb = make_float2(s4.z, s4.w);

#define GAT_STEP(RR, EPAIR)                                    \
            {                                                  \
                float2 ua = f2_add(sa, t2[RR][0]);             \
                float2 ub = f2_add(sb, t2[RR][1]);             \
                ua.x = fmaxf(ua.x, 0.f);  ua.y = fmaxf(ua.y, 0.f); \
                ub.x = fmaxf(ub.x, 0.f);  ub.y = fmaxf(ub.y, 0.f); \
                acc[RR][0] = f2_fma((EPAIR), ua, acc[RR][0]);  \
                acc[RR][1] = f2_fma((EPAIR), ub, acc[RR][1]);  \
            }
            GAT_STEP(0, make_float2(e4.x, e4.y))
            GAT_STEP(1, make_float2(e4.z, e4.w))
#undef GAT_STEP
        }
    }

    // --- epilogue: reduce 16 warp-partials, normalize, store ----------------
    __syncthreads();                       // everyone done reading att2
    float* part = reinterpret_cast<float*>(att2);   // reuse: [16][TI][DD]
#pragma unroll
    for (int rr = 0; rr < 2; ++rr) {
        float4 v = make_float4(acc[rr][0].x, acc[rr][0].y,
                               acc[rr][1].x, acc[rr][1].y);
        *reinterpret_cast<float4*>(
            &part[(wid * TI + 2 * h + rr) * DD + 4 * q]) = v;
    }
    __syncthreads();

    if (tid < TI * DD) {                   // 256 threads: (rr, d)
        int rr = tid >> 6;
        int d  = tid & 63;
        float s = 0.f;
#pragma unroll
        for (int g = 0; g < 16; ++g)
            s += part[(g * TI + rr) * DD + d];
        out[(row0 + rr) * DD + d] = s * rowinv[rr];
    }
}

// ---------------------------------------------------------------------------
// Inputs (metadata order): 0 x[1024,64] f32, 1 adj[1024,1024] i32,
// 2 src i64 (unused), 3 tgt i64 (unused), 4 Msrc (unused), 5 Mtgt (unused),
// 6 f_w[64,128] f32, 7 f_b[64] f32, 8 w_w[1,128] f32, 9 w_b[1] f32 (cancels).
// Output: o[1024,64] f32.
// ---------------------------------------------------------------------------
extern "C" void kernel_launch(void* const* d_in, const int* in_sizes, int n_in,
                              void* d_out, int out_size)
{
    const float* x   = (const float*)d_in[0];
    const int*   adj = (const int*)d_in[1];
    const float* f_w = (const float*)d_in[6];
    const float* f_b = (const float*)d_in[7];
    const float* w_w = (const float*)d_in[8];
    float* out = (float*)d_out;

    cudaFuncSetAttribute(gat_main_kernel,
                         cudaFuncAttributeMaxDynamicSharedMemorySize,
                         SMEM_TOTAL);

    gat_pre_kernel<<<128, 512>>>(x, f_w, f_b, w_w);
    gat_main_kernel<<<NN / TI, 512, SMEM_TOTAL>>>(adj, out);
}

// round 5
// speedup vs baseline: 1.1179x; 1.1179x over previous
#include <cuda_runtime.h>
#include <math.h>
#include <stdint.h>

#define NN 1024
#define DD 64
#define TI 4

// Scratch (device globals — no allocation allowed in kernel_launch).
// g_ssrc padded: depth-2 prefetch may overrun by up to 2 rows (128 floats).
__device__ float g_s1[NN];
__device__ float g_ssrc[NN * DD + 256];
__device__ float g_t[NN * DD];

// ---- packed fp32x2 helpers (sm_100a: ADD2 / FFMA2) -------------------------
__device__ __forceinline__ float2 f2_add(float2 a, float2 b) {
    float2 c;
    asm("add.rn.f32x2 %0, %1, %2;"
        : "=l"(*reinterpret_cast<unsigned long long*>(&c))
        : "l"(*reinterpret_cast<const unsigned long long*>(&a)),
          "l"(*reinterpret_cast<const unsigned long long*>(&b)));
    return c;
}
__device__ __forceinline__ float2 f2_fma(float2 a, float2 b, float2 c) {
    float2 d;
    asm("fma.rn.f32x2 %0, %1, %2, %3;"
        : "=l"(*reinterpret_cast<unsigned long long*>(&d))
        : "l"(*reinterpret_cast<const unsigned long long*>(&a)),
          "l"(*reinterpret_cast<const unsigned long long*>(&b)),
          "l"(*reinterpret_cast<const unsigned long long*>(&c)));
    return d;
}

// ---------------------------------------------------------------------------
// Kernel A: per-node projections. 128 blocks x 512 threads, 8 nodes/block.
// ---------------------------------------------------------------------------
__global__ __launch_bounds__(512, 1) void gat_pre_kernel(
    const float* __restrict__ x,
    const float* __restrict__ f_w,   // [DD][2*DD] row-major
    const float* __restrict__ f_b,   // [DD]
    const float* __restrict__ w_w)   // [1][2*DD]
{
    __shared__ float fw_sh[128][65]; // fw_sh[k][d] = f_w[d*128 + k]
    __shared__ float xs[8][DD];
    __shared__ float w1_sh[DD];
    __shared__ float sred[8][2];

    const int tid   = threadIdx.x;
    const int node0 = blockIdx.x * 8;

    for (int i = tid; i < DD * 128; i += 512)
        fw_sh[i & 127][i >> 7] = f_w[i];          // stride-65: no conflicts
    if (tid < DD) w1_sh[tid] = w_w[tid];
    xs[tid >> 6][tid & 63] = x[node0 * DD + tid];
    __syncthreads();

    const int ln   = tid >> 6;
    const int d    = tid & 63;
    const int node = node0 + ln;

    float a1 = 0.f, a2 = 0.f;
#pragma unroll
    for (int k = 0; k < DD; ++k) {
        float xa = xs[ln][k];
        a1 = fmaf(xa, fw_sh[k][d], a1);
        a2 = fmaf(xa, fw_sh[DD + k][d], a2);
    }
    g_ssrc[node * DD + d] = a1;
    g_t[node * DD + d]    = a2 + f_b[d];

    float p = xs[ln][d] * w1_sh[d];
#pragma unroll
    for (int off = 16; off > 0; off >>= 1)
        p += __shfl_down_sync(0xffffffffu, p, off);
    if ((tid & 31) == 0) sred[ln][(tid >> 5) & 1] = p;
    __syncthreads();
    if (d == 0) g_s1[node] = sred[ln][0] + sred[ln][1];
}

// ---------------------------------------------------------------------------
// Kernel B: masked softmax + weighted-relu contraction.
// 256 blocks (TI=4 rows) x 512 threads, 2 CTAs/SM. R3 structure + explicit
// depth-2 software pipeline on the s (LDG.128) and e (LDS.128) streams.
// Manual static smem layout so prefetch overrun past att2 lands in s1_sh.
// ---------------------------------------------------------------------------
#define SM_ATT   0                      // float2 att2[NN*TI]     32768 B
#define SM_S1    (NN * TI * 8)          // float  s1_sh[NN]        4096 B
#define SM_T     (SM_S1 + NN * 4)       // float  t_sh[TI*DD]      1024 B
#define SM_WSUM  (SM_T + TI * DD * 4)   // float  wsum[16*TI]       256 B
#define SM_RINV  (SM_WSUM + 64 * 4)     // float  rowinv[TI]
#define SM_SIZE  (SM_RINV + 64)

__global__ __launch_bounds__(512, 2) void gat_main_kernel(
    const int* __restrict__ adj,
    float* __restrict__ out)
{
    __shared__ __align__(16) char sm[SM_SIZE];
    float2* att2   = reinterpret_cast<float2*>(sm + SM_ATT);
    float*  s1_sh  = reinterpret_cast<float*>(sm + SM_S1);
    float*  t_sh   = reinterpret_cast<float*>(sm + SM_T);
    float*  wsum   = reinterpret_cast<float*>(sm + SM_WSUM);
    float*  rowinv = reinterpret_cast<float*>(sm + SM_RINV);

    const int tid  = threadIdx.x;
    const int row0 = blockIdx.x * TI;
    const int wid  = tid >> 5;
    const int lane = tid & 31;

    for (int i = tid; i < NN; i += 512) s1_sh[i] = g_s1[i];
    if (tid < TI * DD) t_sh[tid] = g_t[row0 * DD + tid];
    __syncthreads();

    // --- softmax numerators: e[j][r] = adj[r][j]>0 ? exp(s1[j]) : 0 ---------
    {
        float ls[TI] = {0.f, 0.f, 0.f, 0.f};
#pragma unroll
        for (int k = 0; k < 2; ++k) {
            int j = wid * 64 + k * 32 + lane;
            float ev = __expf(s1_sh[j]);
#pragma unroll
            for (int rr = 0; rr < TI; ++rr) {
                int a = adj[(row0 + rr) * NN + j];          // coalesced
                float e = (a > 0) ? ev : 0.f;
                att2[j * TI + rr] = make_float2(e, e);
                ls[rr] += e;
            }
        }
#pragma unroll
        for (int rr = 0; rr < TI; ++rr) {
            float v = ls[rr];
#pragma unroll
            for (int off = 16; off > 0; off >>= 1)
                v += __shfl_xor_sync(0xffffffffu, v, off);
            if (lane == 0) wsum[wid * TI + rr] = v;
        }
    }
    __syncthreads();
    if (tid < TI) {
        float s = 0.f;
#pragma unroll
        for (int g = 0; g < 16; ++g) s += wsum[g * TI + tid];
        rowinv[tid] = 1.f / s;
    }

    // --- contraction: acc[r] += e[j][r] * relu(s_src[j] + t[r]) -------------
    const int h  = lane >> 4;        // 0: rows {0,1}, 1: rows {2,3}
    const int q  = lane & 15;        // d quad: d = 4q..4q+3
    const int jg = wid;              // j group: [jg*64, (jg+1)*64)

    float2 t2[2][2];
#pragma unroll
    for (int rr = 0; rr < 2; ++rr)
#pragma unroll
        for (int p = 0; p < 2; ++p)
            t2[rr][p] = *reinterpret_cast<const float2*>(
                &t_sh[(2 * h + rr) * DD + 4 * q + 2 * p]);

    float2 acc[2][2];
    acc[0][0] = acc[0][1] = acc[1][0] = acc[1][1] = make_float2(0.f, 0.f);

    const float4* __restrict__ sp4 =
        reinterpret_cast<const float4*>(g_ssrc + jg * 64 * DD) + q;
    const float4* __restrict__ ap4 =
        reinterpret_cast<const float4*>(att2 + jg * 64 * TI) + h;

    // depth-2 pipeline: loads for k and k+1 live in named regs one double-step
    // ahead of use. Prefetch at k=62/63 overruns (padded g_ssrc / smem s1_sh).
    float4 sN0 = sp4[0];
    float4 sN1 = sp4[16];
    float4 eN0 = ap4[0];
    float4 eN1 = ap4[2];

#pragma unroll 4
    for (int k = 0; k < 64; k += 2) {
        float4 s0 = sN0, s1 = sN1;
        float4 e0 = eN0, e1 = eN1;
        sN0 = sp4[(k + 2) * 16];
        sN1 = sp4[(k + 3) * 16];
        eN0 = ap4[(k + 2) * 2];
        eN1 = ap4[(k + 3) * 2];

#define GAT_STEP(SS, RR, EPAIR)                                   \
        {                                                         \
            float2 sa = make_float2((SS).x, (SS).y);              \
            float2 sb = make_float2((SS).z, (SS).w);              \
            float2 ua = f2_add(sa, t2[RR][0]);                    \
            float2 ub = f2_add(sb, t2[RR][1]);                    \
            ua.x = fmaxf(ua.x, 0.f);  ua.y = fmaxf(ua.y, 0.f);    \
            ub.x = fmaxf(ub.x, 0.f);  ub.y = fmaxf(ub.y, 0.f);    \
            acc[RR][0] = f2_fma((EPAIR), ua, acc[RR][0]);         \
            acc[RR][1] = f2_fma((EPAIR), ub, acc[RR][1]);         \
        }
        GAT_STEP(s0, 0, make_float2(e0.x, e0.y))
        GAT_STEP(s0, 1, make_float2(e0.z, e0.w))
        GAT_STEP(s1, 0, make_float2(e1.x, e1.y))
        GAT_STEP(s1, 1, make_float2(e1.z, e1.w))
#undef GAT_STEP
    }

    // --- epilogue: reduce 16 warp-partials, normalize, store ----------------
    __syncthreads();                       // everyone done reading att2
    float* part = reinterpret_cast<float*>(att2);   // reuse: [16][TI][DD]
#pragma unroll
    for (int rr = 0; rr < 2; ++rr) {
        float4 v = make_float4(acc[rr][0].x, acc[rr][0].y,
                               acc[rr][1].x, acc[rr][1].y);
        *reinterpret_cast<float4*>(
            &part[(jg * TI + 2 * h + rr) * DD + 4 * q]) = v;
    }
    __syncthreads();

    if (tid < TI * DD) {                   // 256 threads: (rr, d)
        int rr = tid >> 6;
        int d  = tid & 63;
        float s = 0.f;
#pragma unroll
        for (int g = 0; g < 16; ++g)
            s += part[(g * TI + rr) * DD + d];
        out[(row0 + rr) * DD + d] = s * rowinv[rr];
    }
}

// ---------------------------------------------------------------------------
// Inputs (metadata order): 0 x[1024,64] f32, 1 adj[1024,1024] i32,
// 2 src i64 (unused), 3 tgt i64 (unused), 4 Msrc (unused), 5 Mtgt (unused),
// 6 f_w[64,128] f32, 7 f_b[64] f32, 8 w_w[1,128] f32, 9 w_b[1] f32 (cancels).
// Output: o[1024,64] f32.
// ---------------------------------------------------------------------------
extern "C" void kernel_launch(void* const* d_in, const int* in_sizes, int n_in,
                              void* d_out, int out_size)
{
    const float* x   = (const float*)d_in[0];
    const int*   adj = (const int*)d_in[1];
    const float* f_w = (const float*)d_in[6];
    const float* f_b = (const float*)d_in[7];
    const float* w_w = (const float*)d_in[8];
    float* out = (float*)d_out;

    gat_pre_kernel<<<128, 512>>>(x, f_w, f_b, w_w);
    gat_main_kernel<<<NN / TI, 512>>>(adj, out);
}